// round 12
// baseline (speedup 1.0000x reference)
#include <cuda_runtime.h>
#include <cuda_bf16.h>
#include <cstdint>

#define BATCH   1024
#define IN_DIM  512
#define OUT_DIM 512
#define MOD_DIM 256
#define EPS_F   1e-8f
#define NBLK    128

// ---------------- device scratch (allocation-free rule) ----------------
__device__ __align__(16) __nv_bfloat16 g_mod_hi[BATCH * MOD_DIM];
__device__ __align__(16) __nv_bfloat16 g_mod_lo[BATCH * MOD_DIM];
__device__ __align__(16) __nv_bfloat16 g_mw_hi[IN_DIM * MOD_DIM];
__device__ __align__(16) __nv_bfloat16 g_mw_lo[IN_DIM * MOD_DIM];
__device__ __align__(16) __nv_bfloat16 g_w_hi[OUT_DIM * IN_DIM];
__device__ __align__(16) __nv_bfloat16 g_w_lo[OUT_DIM * IN_DIM];
__device__ __align__(16) __nv_bfloat16 g_y_hi[BATCH * IN_DIM];
__device__ __align__(16) __nv_bfloat16 g_y_lo[BATCH * IN_DIM];
__device__ float g_cn[IN_DIM];
__device__ unsigned int g_count;
__device__ volatile unsigned int g_gen;

// ---------------- base-ISA PTX helpers ----------------
__device__ __forceinline__ uint32_t smem_u32(const void* p) {
    uint32_t a;
    asm("{ .reg .u64 t; cvta.to.shared.u64 t, %1; cvt.u32.u64 %0, t; }" : "=r"(a) : "l"(p));
    return a;
}
__device__ __forceinline__ void cp16(uint32_t dst, const void* src) {
    asm volatile("cp.async.cg.shared.global [%0], [%1], 16;" :: "r"(dst), "l"(src));
}
#define CP_COMMIT() asm volatile("cp.async.commit_group;" ::: "memory")
#define CP_WAIT(n)  asm volatile("cp.async.wait_group %0;" :: "n"(n) : "memory")

__device__ __forceinline__ void ldsm4(uint32_t* r, uint32_t addr) {
    asm volatile("ldmatrix.sync.aligned.m8n8.x4.shared.b16 {%0,%1,%2,%3}, [%4];"
        : "=r"(r[0]), "=r"(r[1]), "=r"(r[2]), "=r"(r[3]) : "r"(addr));
}
__device__ __forceinline__ void ldsm2(uint32_t* r, uint32_t addr) {
    asm volatile("ldmatrix.sync.aligned.m8n8.x2.shared.b16 {%0,%1}, [%2];"
        : "=r"(r[0]), "=r"(r[1]) : "r"(addr));
}
__device__ __forceinline__ void mma_bf16(float* d, const uint32_t* a, const uint32_t* b) {
    asm volatile("mma.sync.aligned.m16n8k16.row.col.f32.bf16.bf16.f32 "
        "{%0,%1,%2,%3}, {%4,%5,%6,%7}, {%8,%9}, {%0,%1,%2,%3};"
        : "+f"(d[0]), "+f"(d[1]), "+f"(d[2]), "+f"(d[3])
        : "r"(a[0]), "r"(a[1]), "r"(a[2]), "r"(a[3]), "r"(b[0]), "r"(b[1]));
}

// Grid barrier (validated). All NBLK blocks co-resident (one wave).
__device__ __forceinline__ void grid_barrier() {
    __threadfence();
    __syncthreads();
    if (threadIdx.x == 0) {
        unsigned int gen = g_gen;
        if (atomicAdd(&g_count, 1) == NBLK - 1) {
            g_count = 0;
            __threadfence();
            g_gen = gen + 1;
        } else {
            while (g_gen == gen) { }
        }
        __threadfence();
    }
    __syncthreads();
}

// ---------------- smem: 2 buffers x {Ah, Al, Bh, Bl} 64x32-bf16 tiles ----------
// Row padded to 80 B -> ldmatrix phase-conflict-free.
#define PADB  80
#define TILEB (64 * PADB)     // 5120 B
#define BUFB  (4 * TILEB)     // 20480 B

// 256 threads: thread = (tile 0..3, row 0..63); 4x cp16 per thread (64 B row).
__device__ __forceinline__ void load_chunk(
    uint32_t sb,
    const __nv_bfloat16* __restrict__ Ah, const __nv_bfloat16* __restrict__ Al,
    const __nv_bfloat16* __restrict__ Bh, const __nv_bfloat16* __restrict__ Bl,
    int m0, int n0, int K, int kc, int tid)
{
    const int tile = tid >> 6;
    const int r    = tid & 63;
    const __nv_bfloat16* src;
    size_t off;
    switch (tile) {
        case 0: src = Ah; off = (size_t)(m0 + r) * K + kc; break;
        case 1: src = Al; off = (size_t)(m0 + r) * K + kc; break;
        case 2: src = Bh; off = (size_t)(n0 + r) * K + kc; break;
        default: src = Bl; off = (size_t)(n0 + r) * K + kc; break;
    }
    const uint32_t so = sb + (uint32_t)tile * TILEB + (uint32_t)r * PADB;
#pragma unroll
    for (int j = 0; j < 4; j++)
        cp16(so + j * 16, src + off + j * 8);
}

// ---------------------------------------------------------------------------
// 64x64 block tile NT GEMM, 8 warps in 2x4 (warp tile 32x16), mma m16n8k16,
// 3-term bf16 compensation (term-major mma order for ILP), fp32 accumulate,
// cp.async double buffer.
//   EPI==0 : demod -> y_hi/y_lo bf16   EPI==1 : bias -> fp32 out
// ---------------------------------------------------------------------------
template <int EPI>
__device__ __forceinline__ void gemm_phase(
    uint32_t smb,
    const __nv_bfloat16* __restrict__ Ah, const __nv_bfloat16* __restrict__ Al,
    const __nv_bfloat16* __restrict__ Bh, const __nv_bfloat16* __restrict__ Bl,
    int K, int m0, int n0,
    const float* __restrict__ xin, const float* __restrict__ addv,
    float* __restrict__ outp)
{
    const int tid  = threadIdx.x;
    const int wid  = tid >> 5;
    const int lane = tid & 31;
    const int wm = (wid >> 2) * 32;     // warp row offset (0 | 32)
    const int wn = (wid & 3) * 16;      // warp col offset (0,16,32,48)

    float acc[2][2][4] = {};

    const int nch = K >> 5;
    load_chunk(smb, Ah, Al, Bh, Bl, m0, n0, K, 0, tid);
    CP_COMMIT();

    const uint32_t aoff = (uint32_t)(wm + (lane & 15)) * PADB + (lane & 16);
    const uint32_t boff = (uint32_t)(wn + (lane & 7)) * PADB + ((lane & 8) * 2);

    for (int c = 0; c < nch; c++) {
        const uint32_t cb = smb + (uint32_t)(c & 1) * BUFB;
        if (c + 1 < nch) {
            load_chunk(smb + (uint32_t)((c + 1) & 1) * BUFB,
                       Ah, Al, Bh, Bl, m0, n0, K, (c + 1) << 5, tid);
            CP_COMMIT();
            CP_WAIT(1);
        } else {
            CP_WAIT(0);
        }
        __syncthreads();

#pragma unroll
        for (int k16 = 0; k16 < 32; k16 += 16) {
            const uint32_t kb = (uint32_t)k16 * 2;
            uint32_t ah[2][4], al[2][4], bh[2][2], bl[2][2];
#pragma unroll
            for (int mi = 0; mi < 2; mi++) {
                ldsm4(ah[mi], cb + 0 * TILEB + aoff + (uint32_t)mi * 16 * PADB + kb);
                ldsm4(al[mi], cb + 1 * TILEB + aoff + (uint32_t)mi * 16 * PADB + kb);
            }
#pragma unroll
            for (int ni = 0; ni < 2; ni++) {
                ldsm2(bh[ni], cb + 2 * TILEB + boff + (uint32_t)ni * 8 * PADB + kb);
                ldsm2(bl[ni], cb + 3 * TILEB + boff + (uint32_t)ni * 8 * PADB + kb);
            }
            // term-major: 4 independent mmas between same-acc reuses
#pragma unroll
            for (int mi = 0; mi < 2; mi++)
#pragma unroll
                for (int ni = 0; ni < 2; ni++)
                    mma_bf16(acc[mi][ni], ah[mi], bh[ni]);
#pragma unroll
            for (int mi = 0; mi < 2; mi++)
#pragma unroll
                for (int ni = 0; ni < 2; ni++)
                    mma_bf16(acc[mi][ni], ah[mi], bl[ni]);
#pragma unroll
            for (int mi = 0; mi < 2; mi++)
#pragma unroll
                for (int ni = 0; ni < 2; ni++)
                    mma_bf16(acc[mi][ni], al[mi], bh[ni]);
        }
        __syncthreads();
    }

    // ---- epilogue. D frag: {c0,c1}=row g cols 2t..; {c2,c3}=row g+8.
    const int g = lane >> 2, t = lane & 3;

    if (EPI == 0) {
        float2 mb[2], cn2[2];
#pragma unroll
        for (int ni = 0; ni < 2; ni++) {
            const int col = n0 + wn + 8 * ni + 2 * t;
            mb[ni]  = *(const float2*)(addv + col);
            cn2[ni] = *(const float2*)(g_cn + col);
        }
#pragma unroll
        for (int mi = 0; mi < 2; mi++)
#pragma unroll
            for (int hf = 0; hf < 2; hf++) {
                const int row = m0 + wm + 16 * mi + g + 8 * hf;
#pragma unroll
                for (int ni = 0; ni < 2; ni++) {
                    const int col = n0 + wn + 8 * ni + 2 * t;
                    float2 xv = *(const float2*)(xin + (size_t)row * IN_DIM + col);
                    const float s0 = acc[mi][ni][2 * hf + 0] + mb[ni].x;
                    const float s1 = acc[mi][ni][2 * hf + 1] + mb[ni].y;
                    const float y0 = xv.x * s0 * rsqrtf(s0 * s0 * cn2[ni].x + EPS_F);
                    const float y1 = xv.y * s1 * rsqrtf(s1 * s1 * cn2[ni].y + EPS_F);
                    const __nv_bfloat16 h0 = __float2bfloat16_rn(y0);
                    const __nv_bfloat16 h1 = __float2bfloat16_rn(y1);
                    const __nv_bfloat16 l0 = __float2bfloat16_rn(y0 - __bfloat162float(h0));
                    const __nv_bfloat16 l1 = __float2bfloat16_rn(y1 - __bfloat162float(h1));
                    *(__nv_bfloat162*)(g_y_hi + (size_t)row * IN_DIM + col) = __halves2bfloat162(h0, h1);
                    *(__nv_bfloat162*)(g_y_lo + (size_t)row * IN_DIM + col) = __halves2bfloat162(l0, l1);
                }
            }
    } else {
        float2 bv[2];
#pragma unroll
        for (int ni = 0; ni < 2; ni++)
            bv[ni] = *(const float2*)(addv + n0 + wn + 8 * ni + 2 * t);
#pragma unroll
        for (int mi = 0; mi < 2; mi++)
#pragma unroll
            for (int hf = 0; hf < 2; hf++) {
                const int row = m0 + wm + 16 * mi + g + 8 * hf;
#pragma unroll
                for (int ni = 0; ni < 2; ni++) {
                    const int col = n0 + wn + 8 * ni + 2 * t;
                    float2 o;
                    o.x = acc[mi][ni][2 * hf + 0] + bv[ni].x;
                    o.y = acc[mi][ni][2 * hf + 1] + bv[ni].y;
                    *(float2*)(outp + (size_t)row * OUT_DIM + col) = o;
                }
            }
    }
}

// ---------------------------------------------------------------------------
// Persistent kernel, grid=128, 256 threads:
//   phase0 : blocks 0-7 colnorm; blocks 8-127 fp32->hi/lo bf16 splits
//   barrier ; phase1 GEMM+demod ; barrier ; phase2 GEMM+bias
// ---------------------------------------------------------------------------
#define N_MOD4 (BATCH * MOD_DIM / 4)
#define N_MW4  (IN_DIM * MOD_DIM / 4)
#define N_W4   (OUT_DIM * IN_DIM / 4)
#define N_TOT4 (N_MOD4 + N_MW4 + N_W4)

__global__ __launch_bounds__(256)
void fused_kernel(const float* __restrict__ modulations,
                  const float* __restrict__ x,
                  const float* __restrict__ weight,
                  const float* __restrict__ bias,
                  const float* __restrict__ mod_w,
                  const float* __restrict__ mod_b,
                  float* __restrict__ out)
{
    __shared__ __align__(16) char smem[2 * BUFB];
    __shared__ float cnsh[256];
    const uint32_t smb = smem_u32(smem);
    const int tid = threadIdx.x;

    // ---- phase 0
    if (blockIdx.x < 8) {
        const int c  = blockIdx.x * 64 + (tid & 63);
        const int rg = tid >> 6;     // 0..3
        float s = 0.f;
#pragma unroll 8
        for (int r = rg; r < OUT_DIM; r += 4) {
            const float v = weight[(size_t)r * IN_DIM + c];
            s += v * v;
        }
        cnsh[tid] = s;
        __syncthreads();
        if (rg == 0)
            g_cn[c] = cnsh[tid] + cnsh[tid + 64] + cnsh[tid + 128] + cnsh[tid + 192];
    } else {
        const int stride = 120 * 256;
        for (int tq = (blockIdx.x - 8) * 256 + tid; tq < N_TOT4; tq += stride) {
            const float* src;
            __nv_bfloat16 *ph, *pl;
            size_t e;
            if (tq < N_MOD4)              { src = modulations; ph = g_mod_hi; pl = g_mod_lo; e = (size_t)tq * 4; }
            else if (tq < N_MOD4 + N_MW4) { src = mod_w;       ph = g_mw_hi;  pl = g_mw_lo;  e = (size_t)(tq - N_MOD4) * 4; }
            else                          { src = weight;      ph = g_w_hi;   pl = g_w_lo;   e = (size_t)(tq - N_MOD4 - N_MW4) * 4; }
            float4 v = *(const float4*)(src + e);
            float f[4] = {v.x, v.y, v.z, v.w};
            __nv_bfloat16 h[4], l[4];
#pragma unroll
            for (int i = 0; i < 4; i++) {
                h[i] = __float2bfloat16_rn(f[i]);
                l[i] = __float2bfloat16_rn(f[i] - __bfloat162float(h[i]));
            }
            *(__nv_bfloat162*)(ph + e)     = __halves2bfloat162(h[0], h[1]);
            *(__nv_bfloat162*)(ph + e + 2) = __halves2bfloat162(h[2], h[3]);
            *(__nv_bfloat162*)(pl + e)     = __halves2bfloat162(l[0], l[1]);
            *(__nv_bfloat162*)(pl + e + 2) = __halves2bfloat162(l[2], l[3]);
        }
    }

    grid_barrier();

    const int bx = blockIdx.x & 7;    // 8 col-tiles of 64
    const int by = blockIdx.x >> 3;   // 16 batch-tiles of 64

    // ---- phase 1: y = demod(mod @ mod_w^T + mod_b)
    gemm_phase<0>(smb, g_mod_hi, g_mod_lo, g_mw_hi, g_mw_lo,
                  MOD_DIM, by * 64, bx * 64, x, mod_b, nullptr);

    grid_barrier();

    // ---- phase 2: out = y @ weight^T + bias
    gemm_phase<1>(smb, g_y_hi, g_y_lo, g_w_hi, g_w_lo,
                  IN_DIM, by * 64, bx * 64, nullptr, bias, out);
}

// ---------------------------------------------------------------------------
extern "C" void kernel_launch(void* const* d_in, const int* in_sizes, int n_in,
                              void* d_out, int out_size) {
    const float* modulations = (const float*)d_in[0];   // [1024, 256]
    const float* x           = (const float*)d_in[1];   // [1024, 512]
    const float* weight      = (const float*)d_in[2];   // [512, 512]
    const float* bias        = (const float*)d_in[3];   // [512]
    const float* mod_w       = (const float*)d_in[4];   // [512, 256]
    const float* mod_b       = (const float*)d_in[5];   // [512]
    float* out = (float*)d_out;                          // [1024, 512]

    fused_kernel<<<NBLK, 256>>>(modulations, x, weight, bias, mod_w, mod_b, out);
}